// round 14
// baseline (speedup 1.0000x reference)
#include <cuda_runtime.h>
#include <cuda_bf16.h>
#include <math.h>
#include <stdint.h>

#define BB   64     // batch
#define TT   512    // query tokens
#define NKV  512    // kv tokens
#define DD   256    // feature dim
#define EPS  1e-5f

// ---------------- scratch (no allocations allowed) ----------------
__device__ __nv_bfloat16 g_xb [BB * TT  * DD];   // MLP output (bf16)
__device__ __nv_bfloat16 g_hb [BB * NKV * DD];   // h converted to bf16
__device__ uint8_t       g_q8 [BB * TT  * DD];   // q in e4m3
__device__ uint8_t       g_k8 [BB * NKV * DD];   // k in e4m3
__device__ uint8_t       g_v8T[BB * DD  * NKV];  // v transposed, e4m3: [b][d][n]
__device__ __nv_bfloat16 g_wT [3 * DD * DD];     // wq^T, wk^T, wv^T (bf16, [n][k])
__device__ float         g_pmax[BB * 4 * DD];    // per-(b,qtile) column max of enc
__device__ int           g_perm[BB];             // batches sorted by vl desc (LPT)

// ---------------- helpers ----------------
__device__ __forceinline__ void mma16(float* c, const unsigned* a, const unsigned* b) {
    asm volatile(
        "mma.sync.aligned.m16n8k16.row.col.f32.bf16.bf16.f32 "
        "{%0,%1,%2,%3},{%4,%5,%6,%7},{%8,%9},{%0,%1,%2,%3};"
        : "+f"(c[0]), "+f"(c[1]), "+f"(c[2]), "+f"(c[3])
        : "r"(a[0]), "r"(a[1]), "r"(a[2]), "r"(a[3]), "r"(b[0]), "r"(b[1]));
}

__device__ __forceinline__ void mma8f(float* c, const unsigned* a, const unsigned* b) {
    asm volatile(
        "mma.sync.aligned.m16n8k32.row.col.f32.e4m3.e4m3.f32 "
        "{%0,%1,%2,%3},{%4,%5,%6,%7},{%8,%9},{%0,%1,%2,%3};"
        : "+f"(c[0]), "+f"(c[1]), "+f"(c[2]), "+f"(c[3])
        : "r"(a[0]), "r"(a[1]), "r"(a[2]), "r"(a[3]), "r"(b[0]), "r"(b[1]));
}

__device__ __forceinline__ void ldsm4(unsigned& r0, unsigned& r1, unsigned& r2, unsigned& r3,
                                      unsigned addr) {
    asm volatile("ldmatrix.sync.aligned.m8n8.x4.shared.b16 {%0,%1,%2,%3},[%4];"
        : "=r"(r0), "=r"(r1), "=r"(r2), "=r"(r3) : "r"(addr));
}

__device__ __forceinline__ void cp16(void* s, const void* g) {
    unsigned sa = (unsigned)__cvta_generic_to_shared(s);
    asm volatile("cp.async.cg.shared.global [%0], [%1], 16;\n" :: "r"(sa), "l"(g));
}

__device__ __forceinline__ unsigned packbf(float a, float b) {
    __nv_bfloat162 t = __floats2bfloat162_rn(a, b);
    return *(unsigned*)&t;
}

// pack 2 floats -> e4m3x2 (lo byte = first arg)
__device__ __forceinline__ unsigned short pk8(float lo, float hi) {
    unsigned short r;
    asm("cvt.rn.satfinite.e4m3x2.f32 %0, %2, %1;" : "=h"(r) : "f"(lo), "f"(hi));
    return r;
}

__device__ __forceinline__ unsigned prmtf(unsigned a, unsigned b, unsigned s) {
    unsigned r;
    asm("prmt.b32 %0, %1, %2, %3;" : "=r"(r) : "r"(a), "r"(b), "r"(s));
    return r;
}

__device__ __forceinline__ float ex2(float x) {
    float r;
    asm("ex2.approx.f32 %0, %1;" : "=f"(r) : "f"(x));
    return r;
}

// swizzle for fp8 Q/K tiles: rows of 256 bytes = 16 chunks of 16B, XOR low 3 chunk bits
__device__ __forceinline__ int sQK8(int row, int kb) {
    int c = kb >> 4;
    c = (c & 8) | ((c ^ row) & 7);
    return row * 256 + c * 16 + (kb & 15);
}
// V fp8 tile: row stride 80B (16*5) -> 8 consecutive rows land on 8 distinct 16B banks
#define VSTR8 80

// ---------------- prep megakernel: conv_h | mlp | transw | sort in one launch ----------------
#define PREP_CONV_BLKS  (BB * NKV / 4)          // 8192
#define PREP_MLP_BLKS   (BB * TT / 8)           // 4096
#define PREP_TW_BLKS    (3 * (DD/32) * (DD/32)) // 192
#define PREP_TOTAL      (PREP_CONV_BLKS + PREP_MLP_BLKS + PREP_TW_BLKS + 1)

__global__ void __launch_bounds__(256) prep_kernel(
    const float* __restrict__ traj, const int* __restrict__ labels,
    const float* __restrict__ h,    const int* __restrict__ vlen,
    const float* __restrict__ emb,  const float* __restrict__ w_mlp,
    const float* __restrict__ b_mlp,const float* __restrict__ ln_g,
    const float* __restrict__ ln_b,
    const float* __restrict__ wq, const float* __restrict__ wk,
    const float* __restrict__ wv,
    __nv_bfloat16* __restrict__ x_out, __nv_bfloat16* __restrict__ hb,
    __nv_bfloat16* __restrict__ wT)
{
    const int bid = blockIdx.x;
    const int tid = threadIdx.x;

    if (bid < PREP_CONV_BLKS) {
        const int r0 = bid * 4;                  // b*NKV + n
        const int b  = r0 >> 9;
        if ((r0 & 511) >= vlen[b]) return;
        const long i = ((long)r0 * DD) + tid * 4;
        const float4 v = *(const float4*)(h + i);
        *(__nv_bfloat162*)(hb + i)     = __floats2bfloat162_rn(v.x, v.y);
        *(__nv_bfloat162*)(hb + i + 2) = __floats2bfloat162_rn(v.z, v.w);
    } else if (bid < PREP_CONV_BLKS + PREP_MLP_BLKS) {
        const int warp = tid >> 5, lane = tid & 31;
        const int row  = (bid - PREP_CONV_BLKS) * 8 + warp;   // b*TT + t
        const int b    = row >> 9;
        const int d0   = lane * 8;

        const float t0 = traj[row * 2 + 0];
        const float t1 = traj[row * 2 + 1];

        float val[8], sum = 0.0f, sq = 0.0f;
        #pragma unroll
        for (int i = 0; i < 8; i++) {
            const int d = d0 + i;
            val[i] = fmaf(t0, w_mlp[d], fmaf(t1, w_mlp[DD + d], b_mlp[d]));
            sum += val[i];
            sq  += val[i] * val[i];
        }
        #pragma unroll
        for (int off = 16; off > 0; off >>= 1) {
            sum += __shfl_xor_sync(0xffffffffu, sum, off);
            sq  += __shfl_xor_sync(0xffffffffu, sq,  off);
        }
        const float mean = sum * (1.0f / DD);
        const float var  = sq * (1.0f / DD) - mean * mean;
        const float rstd = rsqrtf(var + EPS);
        const int   lab  = labels[b];

        unsigned pk[4];
        #pragma unroll
        for (int i = 0; i < 4; i++) {
            float y0 = (val[2*i]   - mean) * rstd * ln_g[d0 + 2*i]   + ln_b[d0 + 2*i];
            float y1 = (val[2*i+1] - mean) * rstd * ln_g[d0 + 2*i+1] + ln_b[d0 + 2*i+1];
            y0 = (y0 > 0.0f) ? y0 : 0.01f * y0;
            y1 = (y1 > 0.0f) ? y1 : 0.01f * y1;
            y0 += emb[lab * DD + d0 + 2*i];
            y1 += emb[lab * DD + d0 + 2*i+1];
            pk[i] = packbf(y0, y1);
        }
        *(uint4*)&x_out[(long)row * DD + d0] = make_uint4(pk[0], pk[1], pk[2], pk[3]);
    } else if (bid < PREP_CONV_BLKS + PREP_MLP_BLKS + PREP_TW_BLKS) {
        __shared__ float t[32][33];
        const int idx = bid - (PREP_CONV_BLKS + PREP_MLP_BLKS);
        const int z   = idx >> 6;
        const int rem = idx & 63;
        const int bx  = rem & 7, by = rem >> 3;
        const int tx  = tid & 31, ty = tid >> 5;
        const float* src = (z == 0) ? wq : (z == 1 ? wk : wv);
        const int x = bx * 32 + tx;              // n
        const int y = by * 32 + ty;              // k
        #pragma unroll
        for (int i = 0; i < 32; i += 8)
            t[ty + i][tx] = src[(y + i) * DD + x];
        __syncthreads();
        const int xo = by * 32 + tx;             // k
        const int yo = bx * 32 + ty;             // n
        __nv_bfloat16* dst = wT + (long)z * DD * DD;
        #pragma unroll
        for (int i = 0; i < 32; i += 8)
            dst[(yo + i) * DD + xo] = __float2bfloat16_rn(t[tx][ty + i]);
    } else {
        // ---- LPT sort: rank batches by valid_len descending (deterministic) ----
        if (tid < BB) {
            const int v = vlen[tid];
            int rank = 0;
            #pragma unroll 8
            for (int j = 0; j < BB; j++) {
                const int vj = vlen[j];
                if (vj > v || (vj == v && j < tid)) rank++;
            }
            g_perm[rank] = tid;
        }
    }
}

// ---------------- merged QKV projection GEMM (bf16 mainloop, e4m3 outputs) ----------------
__global__ void __launch_bounds__(256) qkv_gemm_kernel(
    const __nv_bfloat16* __restrict__ xb, const __nv_bfloat16* __restrict__ hb,
    const __nv_bfloat16* __restrict__ wT,
    const float* __restrict__ bq, const float* __restrict__ bk, const float* __restrict__ bv,
    uint8_t* __restrict__ q8, uint8_t* __restrict__ k8,
    uint8_t* __restrict__ v8T, const int* __restrict__ vlen)
{
    constexpr int BM = 128, BN = 128, BK = 32, K = DD, N = DD;
    const int z  = blockIdx.z;
    const int m0 = blockIdx.y * BM;
    const int n0 = blockIdx.x * BN;
    if (z >= 1 && (m0 & 511) >= vlen[m0 >> 9]) return;   // dead key tile

    const __nv_bfloat16* A = (z == 0) ? xb : hb;
    const __nv_bfloat16* B = wT + (long)z * DD * DD;
    const float* bias = (z == 0) ? bq : (z == 1 ? bk : bv);

    __shared__ __align__(16) __nv_bfloat16 As[3][BM * BK];
    __shared__ __align__(16) __nv_bfloat16 Bs[3][BN * BK];

    const int tid  = threadIdx.x;
    const int lane = tid & 31, wid = tid >> 5;
    const int gid  = lane >> 2, tig = lane & 3;
    const int wm   = (wid >> 2) * 64;
    const int wn   = (wid & 3) * 32;

    float acc[4][4][4] = {};

    auto sidx = [](int row, int kk) -> int {
        return row * 32 + ((((kk >> 3) ^ (row >> 1)) & 3) << 3) + (kk & 7);
    };

    auto loadAB = [&](int st, int k0) {
        #pragma unroll
        for (int i = 0; i < 2; i++) {
            int f = tid + i * 256, row = f >> 2, c8 = (f & 3) * 8;
            cp16(&As[st][sidx(row, c8)], &A[(long)(m0 + row) * K + k0 + c8]);
        }
        #pragma unroll
        for (int i = 0; i < 2; i++) {
            int f = tid + i * 256, row = f >> 2, c8 = (f & 3) * 8;
            cp16(&Bs[st][sidx(row, c8)], &B[(long)(n0 + row) * K + k0 + c8]);
        }
    };

    const int nk = K / BK;                      // 8
    loadAB(0, 0);
    asm volatile("cp.async.commit_group;\n");
    loadAB(1, BK);
    asm volatile("cp.async.commit_group;\n");

    const int mi = lane >> 3;
    int st = 0;
    for (int kt = 0; kt < nk; kt++) {
        if (kt + 1 < nk) asm volatile("cp.async.wait_group 1;\n");
        else             asm volatile("cp.async.wait_group 0;\n");
        __syncthreads();

        if (kt + 2 < nk) {
            int s2 = st + 2; if (s2 >= 3) s2 -= 3;
            loadAB(s2, (kt + 2) * BK);
            asm volatile("cp.async.commit_group;\n");
        }

        #pragma unroll
        for (int ks = 0; ks < BK; ks += 16) {
            unsigned af[4][4], bfr[4][2];
            #pragma unroll
            for (int mt = 0; mt < 4; mt++) {
                const int row = wm + mt * 16 + (lane & 7) + (mi & 1) * 8;
                const int kk  = ks + (mi >> 1) * 8;
                unsigned a = (unsigned)__cvta_generic_to_shared(&As[st][sidx(row, kk)]);
                ldsm4(af[mt][0], af[mt][1], af[mt][2], af[mt][3], a);
            }
            #pragma unroll
            for (int p = 0; p < 2; p++) {
                const int n  = wn + p * 16 + (mi >> 1) * 8 + (lane & 7);
                const int kk = ks + (mi & 1) * 8;
                unsigned a = (unsigned)__cvta_generic_to_shared(&Bs[st][sidx(n, kk)]);
                ldsm4(bfr[2 * p][0], bfr[2 * p][1], bfr[2 * p + 1][0], bfr[2 * p + 1][1], a);
            }
            #pragma unroll
            for (int mt = 0; mt < 4; mt++)
                #pragma unroll
                for (int nt = 0; nt < 4; nt++)
                    mma16(acc[mt][nt], af[mt], bfr[nt]);
        }
        if (++st >= 3) st -= 3;
    }

    #pragma unroll
    for (int mt = 0; mt < 4; mt++) {
        const int r0 = m0 + wm + mt * 16 + gid;
        #pragma unroll
        for (int nt = 0; nt < 4; nt++) {
            const int c0 = n0 + wn + nt * 8 + 2 * tig;
            const float b0 = bias[c0], b1 = bias[c0 + 1];
            if (z < 2) {
                uint8_t* C = (z == 0) ? q8 : k8;
                *(unsigned short*)&C[(long)r0 * N + c0] =
                    pk8(acc[mt][nt][0] + b0, acc[mt][nt][1] + b1);
                *(unsigned short*)&C[(long)(r0 + 8) * N + c0] =
                    pk8(acc[mt][nt][2] + b0, acc[mt][nt][3] + b1);
            } else {
                const int bz0 = r0 >> 9, nl0 = r0 & 511;
                v8T[((long)(bz0 * DD + c0    )) * NKV + nl0] = (uint8_t)(pk8(acc[mt][nt][0] + b0, 0.0f) & 0xff);
                v8T[((long)(bz0 * DD + c0 + 1)) * NKV + nl0] = (uint8_t)(pk8(acc[mt][nt][1] + b1, 0.0f) & 0xff);
                const int r1 = r0 + 8, bz1 = r1 >> 9, nl1 = r1 & 511;
                v8T[((long)(bz1 * DD + c0    )) * NKV + nl1] = (uint8_t)(pk8(acc[mt][nt][2] + b0, 0.0f) & 0xff);
                v8T[((long)(bz1 * DD + c0 + 1)) * NKV + nl1] = (uint8_t)(pk8(acc[mt][nt][3] + b1, 0.0f) & 0xff);
            }
        }
    }
}

// ---------------- fused flash attention + maxpool (fp8 e4m3, LPT block order) ----------------
// smem: Q 128x256B (32KB) | K 2x 64x256B (32KB) | V 2x 256xVSTR8 (40KB) = 104KB
#define FLASH_SMEM (128 * 256 + 2 * 64 * 256 + 2 * 256 * VSTR8)

__global__ void __launch_bounds__(256, 1) flash_kernel(
    const uint8_t* __restrict__ q8, const uint8_t* __restrict__ k8,
    const uint8_t* __restrict__ v8T, const int* __restrict__ vlen,
    float* __restrict__ pmax)
{
    extern __shared__ __align__(16) uint8_t sm8[];
    uint8_t* Qs = sm8;                     // 32768
    uint8_t* Ks = sm8 + 128 * 256;         // 2 x 16384
    uint8_t* Vs = Ks + 2 * 64 * 256;       // 2 x 20480

    const int item = blockIdx.x;           // LPT order
    const int b  = g_perm[item >> 2];
    const int qt = item & 3;
    const int tid = threadIdx.x, lane = tid & 31, warp = tid >> 5;
    const int gid = lane >> 2, tig = lane & 3;
    const int vl = vlen[b];
    const int nkt = (vl + 63) >> 6;

    const float CSC = 0.0625f * 1.4426950408889634f;   // exp(s/16)=exp2(s*CSC)

    auto loadK = [&](int st, int t) {
        const uint8_t* g = k8 + ((long)(b * NKV + t * 64)) * DD;
        #pragma unroll
        for (int i = 0; i < 4; i++) {
            int f = tid + i * 256, row = f >> 4, kb = (f & 15) * 16;
            cp16(&Ks[st * 64 * 256 + sQK8(row, kb)], g + (long)row * DD + kb);
        }
    };
    auto loadV = [&](int st, int t) {
        const uint8_t* g = v8T + (long)b * DD * NKV + t * 64;
        #pragma unroll
        for (int i = 0; i < 4; i++) {
            int f = tid + i * 256, row = f >> 2, kb = (f & 3) * 16;
            cp16(&Vs[st * 256 * VSTR8 + row * VSTR8 + kb], g + (long)row * NKV + kb);
        }
    };

    {
        const uint8_t* g = q8 + ((long)(b * TT + qt * 128)) * DD;
        #pragma unroll
        for (int i = 0; i < 8; i++) {
            int f = tid + i * 256, row = f >> 4, kb = (f & 15) * 16;
            cp16(&Qs[sQK8(row, kb)], g + (long)row * DD + kb);
        }
    }
    loadK(0, 0); loadV(0, 0);
    asm volatile("cp.async.commit_group;\n");
    if (nkt > 1) {
        loadK(1, 1); loadV(1, 1);
        asm volatile("cp.async.commit_group;\n");
    }

    float o[32][4];
    #pragma unroll
    for (int dt = 0; dt < 32; dt++)
        #pragma unroll
        for (int j = 0; j < 4; j++) o[dt][j] = 0.0f;
    float l0 = 0.0f, l1 = 0.0f;

    const unsigned selp = (tig >> 1) ? 0x7632u : 0x5410u;
    const int sh0 = (lane & ~3) + 2 * (tig & 1);

    for (int kt = 0; kt < nkt; kt++) {
        if (kt + 1 < nkt) asm volatile("cp.async.wait_group 1;\n");
        else              asm volatile("cp.async.wait_group 0;\n");
        __syncthreads();
        const int st = kt & 1;
        const uint8_t* Kst = Ks + st * 64 * 256;
        const uint8_t* Vst = Vs + st * 256 * VSTR8;

        // S = Q @ K^T, fp8 m16n8k32, kc over 8 chunks of 32 bytes
        float sa[8][4] = {};
        #pragma unroll
        for (int kc = 0; kc < 8; kc++) {
            unsigned af[4];
            {
                const int row = warp * 16 + (lane & 7) + ((lane >> 3) & 1) * 8;
                const int kb  = kc * 32 + ((lane >> 4) & 1) * 16;
                ldsm4(af[0], af[1], af[2], af[3],
                      (unsigned)__cvta_generic_to_shared(&Qs[sQK8(row, kb)]));
            }
            unsigned bfk[8][2];
            #pragma unroll
            for (int p = 0; p < 4; p++) {
                const int n  = p * 16 + ((lane >> 4) & 1) * 8 + (lane & 7);
                const int kb = kc * 32 + ((lane >> 3) & 1) * 16;
                ldsm4(bfk[2 * p][0], bfk[2 * p][1], bfk[2 * p + 1][0], bfk[2 * p + 1][1],
                      (unsigned)__cvta_generic_to_shared(&Kst[sQK8(n, kb)]));
            }
            #pragma unroll
            for (int nt = 0; nt < 8; nt++) mma8f(sa[nt], af, bfk[nt]);
        }

        // p = exp2(s * log2e/16) with key mask; per-thread row-sum partials
        const int base = kt * 64;
        #pragma unroll
        for (int nt = 0; nt < 8; nt++) {
            const int c0 = base + nt * 8 + 2 * tig;
            const float p0 = (c0     < vl) ? ex2(sa[nt][0] * CSC) : 0.0f;
            const float p1 = (c0 + 1 < vl) ? ex2(sa[nt][1] * CSC) : 0.0f;
            const float p2 = (c0     < vl) ? ex2(sa[nt][2] * CSC) : 0.0f;
            const float p3 = (c0 + 1 < vl) ? ex2(sa[nt][3] * CSC) : 0.0f;
            sa[nt][0] = p0; sa[nt][1] = p1; sa[nt][2] = p2; sa[nt][3] = p3;
            l0 += p0 + p1;
            l1 += p2 + p3;
        }

        // convert P to e4m3 fragments for m16n8k32 (butterfly to 4-consecutive-keys layout)
        unsigned pfLo[4], pfHi[4];
        {
            unsigned short pLo[8], pHi[8];
            #pragma unroll
            for (int nt = 0; nt < 8; nt++) {
                pLo[nt] = pk8(sa[nt][0], sa[nt][1]);
                pHi[nt] = pk8(sa[nt][2], sa[nt][3]);
            }
            #pragma unroll
            for (int w = 0; w < 4; w++) {
                unsigned WL = (unsigned)pLo[2*w] | ((unsigned)pLo[2*w+1] << 16);
                unsigned a0 = __shfl_sync(0xffffffffu, WL, sh0);
                unsigned a1 = __shfl_sync(0xffffffffu, WL, sh0 + 1);
                pfLo[w] = prmtf(a0, a1, selp);
                unsigned WH = (unsigned)pHi[2*w] | ((unsigned)pHi[2*w+1] << 16);
                unsigned b0 = __shfl_sync(0xffffffffu, WH, sh0);
                unsigned b1 = __shfl_sync(0xffffffffu, WH, sh0 + 1);
                pfHi[w] = prmtf(b0, b1, selp);
            }
        }

        // O += P @ V : 2 chunks of 32 keys, V rows = d (stride VSTR8, no swizzle)
        #pragma unroll
        for (int kc = 0; kc < 2; kc++) {
            unsigned af2[4] = {pfLo[2*kc], pfHi[2*kc], pfLo[2*kc+1], pfHi[2*kc+1]};
            #pragma unroll
            for (int p = 0; p < 16; p++) {
                const int d  = p * 16 + ((lane >> 4) & 1) * 8 + (lane & 7);
                const int kb = kc * 32 + ((lane >> 3) & 1) * 16;
                unsigned bv[4];
                ldsm4(bv[0], bv[1], bv[2], bv[3],
                      (unsigned)__cvta_generic_to_shared(&Vst[d * VSTR8 + kb]));
                mma8f(o[2 * p],     af2, bv);
                mma8f(o[2 * p + 1], af2, bv + 2);
            }
        }

        __syncthreads();
        if (kt + 2 < nkt) {
            loadK(st, kt + 2); loadV(st, kt + 2);
            asm volatile("cp.async.commit_group;\n");
        }
    }

    asm volatile("cp.async.wait_group 0;\n");
    __syncthreads();

    l0 += __shfl_xor_sync(0xffffffffu, l0, 1);
    l0 += __shfl_xor_sync(0xffffffffu, l0, 2);
    l1 += __shfl_xor_sync(0xffffffffu, l1, 1);
    l1 += __shfl_xor_sync(0xffffffffu, l1, 2);

    float* red = (float*)sm8;
    const float inv0 = 1.0f / l0, inv1 = 1.0f / l1;
    #pragma unroll
    for (int dt = 0; dt < 32; dt++) {
        float c0 = fmaxf(o[dt][0] * inv0, o[dt][2] * inv1);
        float c1 = fmaxf(o[dt][1] * inv0, o[dt][3] * inv1);
        #pragma unroll
        for (int off = 4; off <= 16; off <<= 1) {
            c0 = fmaxf(c0, __shfl_xor_sync(0xffffffffu, c0, off));
            c1 = fmaxf(c1, __shfl_xor_sync(0xffffffffu, c1, off));
        }
        if (gid == 0) {
            red[warp * 256 + dt * 8 + 2 * tig]     = c0;
            red[warp * 256 + dt * 8 + 2 * tig + 1] = c1;
        }
    }
    __syncthreads();
    float mx = red[tid];
    #pragma unroll
    for (int w = 1; w < 8; w++) mx = fmaxf(mx, red[w * 256 + tid]);
    pmax[((long)b * 4 + qt) * DD + tid] = mx;
}

// ---------------- head: combine partial maxes, +emb, dot w_out, sigmoid ----------------
__global__ void __launch_bounds__(256) head_kernel(
    const float* __restrict__ pmax, const int* __restrict__ labels,
    const float* __restrict__ emb, const float* __restrict__ w_out,
    const float* __restrict__ b_out, float* __restrict__ out)
{
    const int b = blockIdx.x;
    const int d = threadIdx.x;
    float m = pmax[((long)b * 4 + 0) * DD + d];
    #pragma unroll
    for (int qt = 1; qt < 4; qt++)
        m = fmaxf(m, pmax[((long)b * 4 + qt) * DD + d]);
    const float pooled = m + emb[labels[b] * DD + d];

    __shared__ float red[256];
    red[d] = pooled * w_out[d];
    __syncthreads();
    #pragma unroll
    for (int off = 128; off > 0; off >>= 1) {
        if (d < off) red[d] += red[d + off];
        __syncthreads();
    }
    if (d == 0) out[b] = 1.0f / (1.0f + expf(-(red[0] + b_out[0])));
}

// ---------------- launch ----------------
extern "C" void kernel_launch(void* const* d_in, const int* in_sizes, int n_in,
                              void* d_out, int out_size)
{
    const float* traj   = (const float*)d_in[0];
    const int*   labels = (const int*)  d_in[1];
    const float* h      = (const float*)d_in[2];
    const int*   vlen   = (const int*)  d_in[3];
    const float* emb    = (const float*)d_in[4];
    const float* w_mlp  = (const float*)d_in[5];
    const float* b_mlp  = (const float*)d_in[6];
    const float* ln_g   = (const float*)d_in[7];
    const float* ln_b   = (const float*)d_in[8];
    const float* wq     = (const float*)d_in[9];
    const float* bq     = (const float*)d_in[10];
    const float* wk     = (const float*)d_in[11];
    const float* bk     = (const float*)d_in[12];
    const float* wv     = (const float*)d_in[13];
    const float* bv     = (const float*)d_in[14];
    const float* w_out  = (const float*)d_in[15];
    const float* b_out  = (const float*)d_in[16];
    float* out = (float*)d_out;

    __nv_bfloat16 *pxb, *phb, *pwT;
    uint8_t *pq8, *pk8_, *pv8;
    float *ppm;
    cudaGetSymbolAddress((void**)&pxb, g_xb);
    cudaGetSymbolAddress((void**)&phb, g_hb);
    cudaGetSymbolAddress((void**)&pq8, g_q8);
    cudaGetSymbolAddress((void**)&pk8_, g_k8);
    cudaGetSymbolAddress((void**)&pv8, g_v8T);
    cudaGetSymbolAddress((void**)&pwT, g_wT);
    cudaGetSymbolAddress((void**)&ppm, g_pmax);

    cudaFuncSetAttribute(flash_kernel, cudaFuncAttributeMaxDynamicSharedMemorySize, FLASH_SMEM);

    // prep megakernel: conv_h | mlp | transw | LPT-sort
    prep_kernel<<<PREP_TOTAL, 256>>>(
        traj, labels, h, vlen, emb, w_mlp, b_mlp, ln_g, ln_b,
        wq, wk, wv, pxb, phb, pwT);

    // merged Q/K/V projections (bf16 mma.sync, e4m3 outputs) with dead-key tile skipping
    {
        dim3 grid(DD / 128, (BB * TT) / 128, 3);
        qkv_gemm_kernel<<<grid, 256>>>(pxb, phb, pwT, bq, bk, bv, pq8, pk8_, pv8, vlen);
    }

    // fp8 fused attention + maxpool, blocks dispatched in LPT (longest-first) order
    flash_kernel<<<BB * 4, 256, FLASH_SMEM>>>(pq8, pk8_, pv8, vlen, ppm);

    // head
    head_kernel<<<BB, 256>>>(ppm, labels, emb, w_out, b_out, out);
}

// round 17
// speedup vs baseline: 1.0340x; 1.0340x over previous
#include <cuda_runtime.h>
#include <cuda_bf16.h>
#include <math.h>
#include <stdint.h>

#define BB   64     // batch
#define TT   512    // query tokens
#define NKV  512    // kv tokens
#define DD   256    // feature dim
#define EPS  1e-5f

// ---------------- scratch (no allocations allowed) ----------------
__device__ __nv_bfloat16 g_xb [BB * TT  * DD];   // MLP output (bf16)
__device__ __nv_bfloat16 g_hb [BB * NKV * DD];   // h converted to bf16
__device__ __nv_bfloat16 g_qb [BB * TT  * DD];
__device__ __nv_bfloat16 g_kb [BB * NKV * DD];
__device__ __nv_bfloat16 g_vT [BB * DD  * NKV];  // v transposed per batch: [b][d][n]
__device__ __nv_bfloat16 g_wT [3 * DD * DD];     // wq^T, wk^T, wv^T (bf16, [n][k])
__device__ float         g_pmax[BB * 4 * DD];    // per-(b,qtile) column max of enc
__device__ int           g_perm[BB];             // batches sorted by vl desc (LPT)

// ---------------- helpers ----------------
__device__ __forceinline__ void mma16(float* c, const unsigned* a, const unsigned* b) {
    asm volatile(
        "mma.sync.aligned.m16n8k16.row.col.f32.bf16.bf16.f32 "
        "{%0,%1,%2,%3},{%4,%5,%6,%7},{%8,%9},{%0,%1,%2,%3};"
        : "+f"(c[0]), "+f"(c[1]), "+f"(c[2]), "+f"(c[3])
        : "r"(a[0]), "r"(a[1]), "r"(a[2]), "r"(a[3]), "r"(b[0]), "r"(b[1]));
}

__device__ __forceinline__ void ldsm4(unsigned& r0, unsigned& r1, unsigned& r2, unsigned& r3,
                                      unsigned addr) {
    asm volatile("ldmatrix.sync.aligned.m8n8.x4.shared.b16 {%0,%1,%2,%3},[%4];"
        : "=r"(r0), "=r"(r1), "=r"(r2), "=r"(r3) : "r"(addr));
}

__device__ __forceinline__ void cp16(void* s, const void* g) {
    unsigned sa = (unsigned)__cvta_generic_to_shared(s);
    asm volatile("cp.async.cg.shared.global [%0], [%1], 16;\n" :: "r"(sa), "l"(g));
}

__device__ __forceinline__ unsigned packbf(float a, float b) {
    __nv_bfloat162 t = __floats2bfloat162_rn(a, b);
    return *(unsigned*)&t;
}

__device__ __forceinline__ float ex2(float x) {
    float r;
    asm("ex2.approx.f32 %0, %1;" : "=f"(r) : "f"(x));
    return r;
}

// swizzles: rows of 256 halves (Q/K tiles) and 64 halves (V tiles)
__device__ __forceinline__ int sQK(int row, int kk) {
    int c = kk >> 3;
    c = (c & 24) | ((c ^ row) & 7);
    return row * 256 + c * 8 + (kk & 7);
}
__device__ __forceinline__ int sV(int row, int kk) {
    int c = ((kk >> 3) ^ row) & 7;
    return row * 64 + c * 8 + (kk & 7);
}

// ---------------- prep megakernel: conv_h | mlp | transw | sort in one launch ----------------
#define PREP_CONV_BLKS  (BB * NKV / 4)          // 8192
#define PREP_MLP_BLKS   (BB * TT / 8)           // 4096
#define PREP_TW_BLKS    (3 * (DD/32) * (DD/32)) // 192
#define PREP_TOTAL      (PREP_CONV_BLKS + PREP_MLP_BLKS + PREP_TW_BLKS + 1)

__global__ void __launch_bounds__(256) prep_kernel(
    const float* __restrict__ traj, const int* __restrict__ labels,
    const float* __restrict__ h,    const int* __restrict__ vlen,
    const float* __restrict__ emb,  const float* __restrict__ w_mlp,
    const float* __restrict__ b_mlp,const float* __restrict__ ln_g,
    const float* __restrict__ ln_b,
    const float* __restrict__ wq, const float* __restrict__ wk,
    const float* __restrict__ wv,
    __nv_bfloat16* __restrict__ x_out, __nv_bfloat16* __restrict__ hb,
    __nv_bfloat16* __restrict__ wT)
{
    const int bid = blockIdx.x;
    const int tid = threadIdx.x;

    if (bid < PREP_CONV_BLKS) {
        const int r0 = bid * 4;                  // b*NKV + n
        const int b  = r0 >> 9;
        if ((r0 & 511) >= vlen[b]) return;
        const long i = ((long)r0 * DD) + tid * 4;
        const float4 v = *(const float4*)(h + i);
        *(__nv_bfloat162*)(hb + i)     = __floats2bfloat162_rn(v.x, v.y);
        *(__nv_bfloat162*)(hb + i + 2) = __floats2bfloat162_rn(v.z, v.w);
    } else if (bid < PREP_CONV_BLKS + PREP_MLP_BLKS) {
        const int warp = tid >> 5, lane = tid & 31;
        const int row  = (bid - PREP_CONV_BLKS) * 8 + warp;   // b*TT + t
        const int b    = row >> 9;
        const int d0   = lane * 8;

        const float t0 = traj[row * 2 + 0];
        const float t1 = traj[row * 2 + 1];

        float val[8], sum = 0.0f, sq = 0.0f;
        #pragma unroll
        for (int i = 0; i < 8; i++) {
            const int d = d0 + i;
            val[i] = fmaf(t0, w_mlp[d], fmaf(t1, w_mlp[DD + d], b_mlp[d]));
            sum += val[i];
            sq  += val[i] * val[i];
        }
        #pragma unroll
        for (int off = 16; off > 0; off >>= 1) {
            sum += __shfl_xor_sync(0xffffffffu, sum, off);
            sq  += __shfl_xor_sync(0xffffffffu, sq,  off);
        }
        const float mean = sum * (1.0f / DD);
        const float var  = sq * (1.0f / DD) - mean * mean;
        const float rstd = rsqrtf(var + EPS);
        const int   lab  = labels[b];

        unsigned pk[4];
        #pragma unroll
        for (int i = 0; i < 4; i++) {
            float y0 = (val[2*i]   - mean) * rstd * ln_g[d0 + 2*i]   + ln_b[d0 + 2*i];
            float y1 = (val[2*i+1] - mean) * rstd * ln_g[d0 + 2*i+1] + ln_b[d0 + 2*i+1];
            y0 = (y0 > 0.0f) ? y0 : 0.01f * y0;
            y1 = (y1 > 0.0f) ? y1 : 0.01f * y1;
            y0 += emb[lab * DD + d0 + 2*i];
            y1 += emb[lab * DD + d0 + 2*i+1];
            pk[i] = packbf(y0, y1);
        }
        *(uint4*)&x_out[(long)row * DD + d0] = make_uint4(pk[0], pk[1], pk[2], pk[3]);
    } else if (bid < PREP_CONV_BLKS + PREP_MLP_BLKS + PREP_TW_BLKS) {
        __shared__ float t[32][33];
        const int idx = bid - (PREP_CONV_BLKS + PREP_MLP_BLKS);
        const int z   = idx >> 6;
        const int rem = idx & 63;
        const int bx  = rem & 7, by = rem >> 3;
        const int tx  = tid & 31, ty = tid >> 5;
        const float* src = (z == 0) ? wq : (z == 1 ? wk : wv);
        const int x = bx * 32 + tx;              // n
        const int y = by * 32 + ty;              // k
        #pragma unroll
        for (int i = 0; i < 32; i += 8)
            t[ty + i][tx] = src[(y + i) * DD + x];
        __syncthreads();
        const int xo = by * 32 + tx;             // k
        const int yo = bx * 32 + ty;             // n
        __nv_bfloat16* dst = wT + (long)z * DD * DD;
        #pragma unroll
        for (int i = 0; i < 32; i += 8)
            dst[(yo + i) * DD + xo] = __float2bfloat16_rn(t[tx][ty + i]);
    } else {
        // ---- LPT sort: rank batches by valid_len descending (deterministic) ----
        if (tid < BB) {
            const int v = vlen[tid];
            int rank = 0;
            #pragma unroll 8
            for (int j = 0; j < BB; j++) {
                const int vj = vlen[j];
                if (vj > v || (vj == v && j < tid)) rank++;
            }
            g_perm[rank] = tid;
        }
    }
}

// ---------------- merged QKV projection GEMM, full-N tile (2-stage, 48KB static) ----------------
// Block 128M x 256N x K=256, BK=32, 512 threads (16 warps 4x4, warp 32x64).
// blockIdx.x = m-tile (256), blockIdx.y = z (q/k/v). Dead K/V tiles skipped.
__global__ void __launch_bounds__(512) qkv_gemm_kernel(
    const __nv_bfloat16* __restrict__ xb, const __nv_bfloat16* __restrict__ hb,
    const __nv_bfloat16* __restrict__ wT,
    const float* __restrict__ bq, const float* __restrict__ bk, const float* __restrict__ bv,
    __nv_bfloat16* __restrict__ qb, __nv_bfloat16* __restrict__ kb,
    __nv_bfloat16* __restrict__ vT, const int* __restrict__ vlen)
{
    constexpr int BM = 128, BN = 256, BK = 32, K = DD, N = DD;
    __shared__ __align__(16) __nv_bfloat16 As[2][BM * BK];   // 16KB
    __shared__ __align__(16) __nv_bfloat16 Bs[2][BN * BK];   // 32KB

    const int z  = blockIdx.y;
    const int m0 = blockIdx.x * BM;
    if (z >= 1 && (m0 & 511) >= vlen[m0 >> 9]) return;   // dead key tile

    const __nv_bfloat16* A = (z == 0) ? xb : hb;
    const __nv_bfloat16* B = wT + (long)z * DD * DD;
    const float* bias = (z == 0) ? bq : (z == 1 ? bk : bv);

    const int tid  = threadIdx.x;
    const int lane = tid & 31, wid = tid >> 5;
    const int gid  = lane >> 2, tig = lane & 3;
    const int wm   = (wid >> 2) * 32;             // 4 m-groups of 32
    const int wn   = (wid & 3) * 64;              // 4 n-groups of 64

    float acc[2][8][4] = {};

    auto sidx = [](int row, int kk) -> int {
        return row * 32 + ((((kk >> 3) ^ (row >> 1)) & 3) << 3) + (kk & 7);
    };

    auto loadAB = [&](int st, int k0) {
        {   // A: 128 rows x 32 halves = 512 chunks of 8 halves
            int row = tid >> 2, c8 = (tid & 3) * 8;
            cp16(&As[st][sidx(row, c8)], &A[(long)(m0 + row) * K + k0 + c8]);
        }
        #pragma unroll
        for (int i = 0; i < 2; i++) {   // B: 256 rows x 32 halves = 1024 chunks
            int f = tid + i * 512, row = f >> 2, c8 = (f & 3) * 8;
            cp16(&Bs[st][sidx(row, c8)], &B[(long)row * K + k0 + c8]);
        }
    };

    const int nk = K / BK;                      // 8
    loadAB(0, 0);
    asm volatile("cp.async.commit_group;\n");

    const int mi = lane >> 3;
    for (int kt = 0; kt < nk; kt++) {
        if (kt + 1 < nk) {
            loadAB((kt + 1) & 1, (kt + 1) * BK);
            asm volatile("cp.async.commit_group;\n");
            asm volatile("cp.async.wait_group 1;\n");
        } else {
            asm volatile("cp.async.wait_group 0;\n");
        }
        __syncthreads();
        const int st = kt & 1;

        #pragma unroll
        for (int ks = 0; ks < BK; ks += 16) {
            unsigned af[2][4], bfr[8][2];
            #pragma unroll
            for (int mt = 0; mt < 2; mt++) {
                const int row = wm + mt * 16 + (lane & 7) + (mi & 1) * 8;
                const int kk  = ks + (mi >> 1) * 8;
                unsigned a = (unsigned)__cvta_generic_to_shared(&As[st][sidx(row, kk)]);
                ldsm4(af[mt][0], af[mt][1], af[mt][2], af[mt][3], a);
            }
            #pragma unroll
            for (int p = 0; p < 4; p++) {
                const int n  = wn + p * 16 + (mi >> 1) * 8 + (lane & 7);
                const int kk = ks + (mi & 1) * 8;
                unsigned a = (unsigned)__cvta_generic_to_shared(&Bs[st][sidx(n, kk)]);
                ldsm4(bfr[2 * p][0], bfr[2 * p][1], bfr[2 * p + 1][0], bfr[2 * p + 1][1], a);
            }
            #pragma unroll
            for (int mt = 0; mt < 2; mt++)
                #pragma unroll
                for (int nt = 0; nt < 8; nt++)
                    mma16(acc[mt][nt], af[mt], bfr[nt]);
        }
        __syncthreads();
    }

    #pragma unroll
    for (int mt = 0; mt < 2; mt++) {
        const int r0 = m0 + wm + mt * 16 + gid;
        #pragma unroll
        for (int nt = 0; nt < 8; nt++) {
            const int c0 = wn + nt * 8 + 2 * tig;
            const float b0 = bias[c0], b1 = bias[c0 + 1];
            if (z < 2) {
                __nv_bfloat16* C = (z == 0) ? qb : kb;
                *(__nv_bfloat162*)&C[(long)r0 * N + c0] =
                    __floats2bfloat162_rn(acc[mt][nt][0] + b0, acc[mt][nt][1] + b1);
                *(__nv_bfloat162*)&C[(long)(r0 + 8) * N + c0] =
                    __floats2bfloat162_rn(acc[mt][nt][2] + b0, acc[mt][nt][3] + b1);
            } else {
                const int bz0 = r0 >> 9, nl0 = r0 & 511;
                vT[((long)(bz0 * DD + c0    )) * NKV + nl0] = __float2bfloat16_rn(acc[mt][nt][0] + b0);
                vT[((long)(bz0 * DD + c0 + 1)) * NKV + nl0] = __float2bfloat16_rn(acc[mt][nt][1] + b1);
                const int r1 = r0 + 8, bz1 = r1 >> 9, nl1 = r1 & 511;
                vT[((long)(bz1 * DD + c0    )) * NKV + nl1] = __float2bfloat16_rn(acc[mt][nt][2] + b0);
                vT[((long)(bz1 * DD + c0 + 1)) * NKV + nl1] = __float2bfloat16_rn(acc[mt][nt][3] + b1);
            }
        }
    }
}

// ---------------- fused flash attention + maxpool (grid-launched, LPT block order) ----------------
__global__ void __launch_bounds__(256, 1) flash_kernel(
    const __nv_bfloat16* __restrict__ qb, const __nv_bfloat16* __restrict__ kb,
    const __nv_bfloat16* __restrict__ vT, const int* __restrict__ vlen,
    float* __restrict__ pmax)
{
    extern __shared__ __nv_bfloat16 sm[];
    __nv_bfloat16* Qs = sm;                    // 128*256
    __nv_bfloat16* Ks = sm + 128 * 256;        // 2 * 64*256
    __nv_bfloat16* Vs = Ks + 2 * 64 * 256;     // 2 * 256*64

    const int item = blockIdx.x;               // 0..255, LPT order
    const int b  = g_perm[item >> 2];
    const int qt = item & 3;
    const int tid = threadIdx.x, lane = tid & 31, warp = tid >> 5;
    const int gid = lane >> 2, tig = lane & 3;
    const int vl = vlen[b];
    const int nkt = (vl + 63) >> 6;

    const float CSC = 0.0625f * 1.4426950408889634f;   // exp(s/16)=exp2(s*CSC)

    auto loadK = [&](int st, int t) {
        const __nv_bfloat16* g = kb + ((long)(b * NKV + t * 64)) * DD;
        #pragma unroll
        for (int i = 0; i < 8; i++) {
            int f = tid + i * 256, row = f >> 5, c8 = (f & 31) * 8;
            cp16(&Ks[st * 64 * 256 + sQK(row, c8)], g + (long)row * DD + c8);
        }
    };
    auto loadV = [&](int st, int t) {
        const __nv_bfloat16* g = vT + (long)b * DD * NKV + t * 64;
        #pragma unroll
        for (int i = 0; i < 8; i++) {
            int f = tid + i * 256, row = f >> 3, c8 = (f & 7) * 8;
            cp16(&Vs[st * 256 * 64 + sV(row, c8)], g + (long)row * NKV + c8);
        }
    };

    {
        const __nv_bfloat16* g = qb + ((long)(b * TT + qt * 128)) * DD;
        #pragma unroll
        for (int i = 0; i < 16; i++) {
            int f = tid + i * 256, row = f >> 5, c8 = (f & 31) * 8;
            cp16(&Qs[sQK(row, c8)], g + (long)row * DD + c8);
        }
    }
    loadK(0, 0); loadV(0, 0);
    asm volatile("cp.async.commit_group;\n");
    if (nkt > 1) {
        loadK(1, 1); loadV(1, 1);
        asm volatile("cp.async.commit_group;\n");
    }

    float o[32][4];
    #pragma unroll
    for (int dt = 0; dt < 32; dt++)
        #pragma unroll
        for (int j = 0; j < 4; j++) o[dt][j] = 0.0f;
    float l0 = 0.0f, l1 = 0.0f;

    for (int kt = 0; kt < nkt; kt++) {
        if (kt + 1 < nkt) asm volatile("cp.async.wait_group 1;\n");
        else              asm volatile("cp.async.wait_group 0;\n");
        __syncthreads();
        const int st = kt & 1;
        const __nv_bfloat16* Kst = Ks + st * 64 * 256;
        const __nv_bfloat16* Vst = Vs + st * 256 * 64;

        float sa[8][4] = {};
        #pragma unroll
        for (int kc = 0; kc < 16; kc++) {
            unsigned af[4];
            {
                const int row = warp * 16 + (lane & 7) + ((lane >> 3) & 1) * 8;
                const int kk  = kc * 16 + ((lane >> 4) & 1) * 8;
                ldsm4(af[0], af[1], af[2], af[3],
                      (unsigned)__cvta_generic_to_shared(&Qs[sQK(row, kk)]));
            }
            unsigned bfk[8][2];
            #pragma unroll
            for (int p = 0; p < 4; p++) {
                const int n  = p * 16 + ((lane >> 4) & 1) * 8 + (lane & 7);
                const int kk = kc * 16 + ((lane >> 3) & 1) * 8;
                ldsm4(bfk[2 * p][0], bfk[2 * p][1], bfk[2 * p + 1][0], bfk[2 * p + 1][1],
                      (unsigned)__cvta_generic_to_shared(&Kst[sQK(n, kk)]));
            }
            #pragma unroll
            for (int nt = 0; nt < 8; nt++) mma16(sa[nt], af, bfk[nt]);
        }

        const int base = kt * 64;
        #pragma unroll
        for (int nt = 0; nt < 8; nt++) {
            const int c0 = base + nt * 8 + 2 * tig;
            const float p0 = (c0     < vl) ? ex2(sa[nt][0] * CSC) : 0.0f;
            const float p1 = (c0 + 1 < vl) ? ex2(sa[nt][1] * CSC) : 0.0f;
            const float p2 = (c0     < vl) ? ex2(sa[nt][2] * CSC) : 0.0f;
            const float p3 = (c0 + 1 < vl) ? ex2(sa[nt][3] * CSC) : 0.0f;
            sa[nt][0] = p0; sa[nt][1] = p1; sa[nt][2] = p2; sa[nt][3] = p3;
            l0 += p0 + p1;
            l1 += p2 + p3;
        }

        unsigned pf[4][4];
        #pragma unroll
        for (int kc = 0; kc < 4; kc++) {
            pf[kc][0] = packbf(sa[2 * kc][0],     sa[2 * kc][1]);
            pf[kc][1] = packbf(sa[2 * kc][2],     sa[2 * kc][3]);
            pf[kc][2] = packbf(sa[2 * kc + 1][0], sa[2 * kc + 1][1]);
            pf[kc][3] = packbf(sa[2 * kc + 1][2], sa[2 * kc + 1][3]);
        }

        #pragma unroll
        for (int kc = 0; kc < 4; kc++) {
            #pragma unroll
            for (int p = 0; p < 16; p++) {
                const int d  = p * 16 + ((lane >> 4) & 1) * 8 + (lane & 7);
                const int kk = kc * 16 + ((lane >> 3) & 1) * 8;
                unsigned bv[4];
                ldsm4(bv[0], bv[1], bv[2], bv[3],
                      (unsigned)__cvta_generic_to_shared(&Vst[sV(d, kk)]));
                mma16(o[2 * p],     pf[kc], bv);
                mma16(o[2 * p + 1], pf[kc], bv + 2);
            }
        }

        __syncthreads();
        if (kt + 2 < nkt) {
            loadK(st, kt + 2); loadV(st, kt + 2);
            asm volatile("cp.async.commit_group;\n");
        }
    }

    asm volatile("cp.async.wait_group 0;\n");
    __syncthreads();

    l0 += __shfl_xor_sync(0xffffffffu, l0, 1);
    l0 += __shfl_xor_sync(0xffffffffu, l0, 2);
    l1 += __shfl_xor_sync(0xffffffffu, l1, 1);
    l1 += __shfl_xor_sync(0xffffffffu, l1, 2);

    float* red = (float*)sm;
    const float inv0 = 1.0f / l0, inv1 = 1.0f / l1;
    #pragma unroll
    for (int dt = 0; dt < 32; dt++) {
        float c0 = fmaxf(o[dt][0] * inv0, o[dt][2] * inv1);
        float c1 = fmaxf(o[dt][1] * inv0, o[dt][3] * inv1);
        #pragma unroll
        for (int off = 4; off <= 16; off <<= 1) {
            c0 = fmaxf(c0, __shfl_xor_sync(0xffffffffu, c0, off));
            c1 = fmaxf(c1, __shfl_xor_sync(0xffffffffu, c1, off));
        }
        if (gid == 0) {
            red[warp * 256 + dt * 8 + 2 * tig]     = c0;
            red[warp * 256 + dt * 8 + 2 * tig + 1] = c1;
        }
    }
    __syncthreads();
    float mx = red[tid];
    #pragma unroll
    for (int w = 1; w < 8; w++) mx = fmaxf(mx, red[w * 256 + tid]);
    pmax[((long)b * 4 + qt) * DD + tid] = mx;
}

// ---------------- head: combine partial maxes, +emb, dot w_out, sigmoid ----------------
__global__ void __launch_bounds__(256) head_kernel(
    const float* __restrict__ pmax, const int* __restrict__ labels,
    const float* __restrict__ emb, const float* __restrict__ w_out,
    const float* __restrict__ b_out, float* __restrict__ out)
{
    const int b = blockIdx.x;
    const int d = threadIdx.x;
    float m = pmax[((long)b * 4 + 0) * DD + d];
    #pragma unroll
    for (int qt = 1; qt < 4; qt++)
        m = fmaxf(m, pmax[((long)b * 4 + qt) * DD + d]);
    const float pooled = m + emb[labels[b] * DD + d];

    __shared__ float red[256];
    red[d] = pooled * w_out[d];
    __syncthreads();
    #pragma unroll
    for (int off = 128; off > 0; off >>= 1) {
        if (d < off) red[d] += red[d + off];
        __syncthreads();
    }
    if (d == 0) out[b] = 1.0f / (1.0f + expf(-(red[0] + b_out[0])));
}

// ---------------- launch ----------------
extern "C" void kernel_launch(void* const* d_in, const int* in_sizes, int n_in,
                              void* d_out, int out_size)
{
    const float* traj   = (const float*)d_in[0];
    const int*   labels = (const int*)  d_in[1];
    const float* h      = (const float*)d_in[2];
    const int*   vlen   = (const int*)  d_in[3];
    const float* emb    = (const float*)d_in[4];
    const float* w_mlp  = (const float*)d_in[5];
    const float* b_mlp  = (const float*)d_in[6];
    const float* ln_g   = (const float*)d_in[7];
    const float* ln_b   = (const float*)d_in[8];
    const float* wq     = (const float*)d_in[9];
    const float* bq     = (const float*)d_in[10];
    const float* wk     = (const float*)d_in[11];
    const float* bk     = (const float*)d_in[12];
    const float* wv     = (const float*)d_in[13];
    const float* bv     = (const float*)d_in[14];
    const float* w_out  = (const float*)d_in[15];
    const float* b_out  = (const float*)d_in[16];
    float* out = (float*)d_out;

    __nv_bfloat16 *pxb, *phb, *pqb, *pkb, *pvT, *pwT;
    float *ppm;
    cudaGetSymbolAddress((void**)&pxb, g_xb);
    cudaGetSymbolAddress((void**)&phb, g_hb);
    cudaGetSymbolAddress((void**)&pqb, g_qb);
    cudaGetSymbolAddress((void**)&pkb, g_kb);
    cudaGetSymbolAddress((void**)&pvT, g_vT);
    cudaGetSymbolAddress((void**)&pwT, g_wT);
    cudaGetSymbolAddress((void**)&ppm, g_pmax);

    const int FLASH_SMEM = (128 * 256 + 2 * 64 * 256 + 2 * 256 * 64) * 2;  // 192KB
    cudaFuncSetAttribute(flash_kernel, cudaFuncAttributeMaxDynamicSharedMemorySize, FLASH_SMEM);

    // prep megakernel: conv_h | mlp | transw | LPT-sort
    prep_kernel<<<PREP_TOTAL, 256>>>(
        traj, labels, h, vlen, emb, w_mlp, b_mlp, ln_g, ln_b,
        wq, wk, wv, pxb, phb, pwT);

    // merged Q/K/V projections (full-N tiles, 2-stage static smem) with dead-key skipping
    {
        dim3 grid((BB * TT) / 128, 3);
        qkv_gemm_kernel<<<grid, 512>>>(pxb, phb, pwT, bq, bk, bv, pqb, pkb, pvT, vlen);
    }

    // fused attention + maxpool, blocks dispatched in LPT (longest-first) order
    flash_kernel<<<BB * 4, 256, FLASH_SMEM>>>(pqb, pkb, pvT, vlen, ppm);

    // head
    head_kernel<<<BB, 256>>>(ppm, labels, emb, w_out, b_out, out);
}